// round 7
// baseline (speedup 1.0000x reference)
#include <cuda_runtime.h>
#include <math.h>

#define NS 512
#define DD 400
#define HH 400
#define HP 416   // padded hidden dim (13 * 32)

typedef unsigned long long u64;

// ---- scratch (no allocations allowed) ----
__device__ float  g_hxT[HP * NS];   // transposed: [h][sample], rows 400..415 zero
__device__ float  g_hyT[HP * NS];   // transposed, b1 folded in, rows 400..415 zero
__device__ float  g_expsum[NS];     // per-row sum of exp(T1) = 1 + e^v
__device__ double g_tsum;           // sum of all T1
__device__ double g_dsum;           // sum of diag T1 (== T0 sum)
__device__ int    g_cnt = 0;

// ---- packed f32x2 helpers (sm_10x) ----
#define PACK2(d, lo, hi) \
    asm("mov.b64 %0, {%1,%2};" : "=l"(d) : "f"(lo), "f"(hi))
#define FMA2(acc, a, b) \
    asm("fma.rn.f32x2 %0, %1, %2, %0;" : "+l"(acc) : "l"(a), "l"(b))
// acc2 += relu(y2 + x2) * w2   (componentwise)
#define RELU_FMA2(acc, y2, x2, w2)                      \
    asm("{\n\t"                                         \
        ".reg .b64 t;\n\t"                              \
        ".reg .f32 lo, hi;\n\t"                         \
        "add.rn.f32x2 t, %1, %2;\n\t"                   \
        "mov.b64 {lo, hi}, t;\n\t"                      \
        "max.f32 lo, lo, 0f00000000;\n\t"               \
        "max.f32 hi, hi, 0f00000000;\n\t"               \
        "mov.b64 t, {lo, hi};\n\t"                      \
        "fma.rn.f32x2 %0, t, %3, %0;\n\t"               \
        "}" : "+l"(acc) : "l"(y2), "l"(x2), "l"(w2))

// ======================================================================
// Kernel 1: dual GEMM, transposed output.
//   z=0: g_hxT[h][m] = sum_k x[m,k] W1[h,k]
//   z=1: g_hyT[h][m] = sum_k y[m,k] W1[h,400+k] + b1[h]
// Rows h in [400,416) are written as zeros (k-padding for pair kernel).
// Tile 64m x 32h, BK=16, 256 threads, thread tile 2h x 4m.
// COALESCED global loads (warp covers contiguous k).
// Double-buffered smem, 1 sync/tile, software-pipelined LDS.
// Grid (8 m, 13 h, 2 z) = 208 blocks.
// ======================================================================
__global__ void __launch_bounds__(256)
gemm_h_kernel(const float* __restrict__ x,
              const float* __restrict__ y,
              const float* __restrict__ W1,
              const float* __restrict__ b1) {
    const int z = blockIdx.z;

    if (z == 0 && blockIdx.x == 0 && blockIdx.y == 0) {
        g_expsum[threadIdx.x] = 0.f;
        g_expsum[threadIdx.x + 256] = 0.f;
        if (threadIdx.x == 0) { g_tsum = 0.0; g_dsum = 0.0; g_cnt = 0; }
    }

    const float* A   = z ? y : x;
    const int   woff = z ? DD : 0;
    float*      outT = z ? g_hyT : g_hxT;

    const int m0 = blockIdx.x * 64;
    const int h0 = blockIdx.y * 32;

    __shared__ __align__(16) float As[2][16][64];  // [buf][k][m]
    __shared__ __align__(16) u64   Hd[2][16][32];  // [buf][k][h] dup'd (w,w)

    const int tid = threadIdx.x;       // 256
    const int tx  = tid & 15;          // m quad: 4 m each
    const int ty  = tid >> 4;          // h pair: 2 h each (0..15)

    // A staging: coalesced — 4 consecutive lanes cover 16 k of one m row
    const int a_m  = tid >> 2;         // 0..63
    const int a_kq = (tid & 3) * 4;    // 0,4,8,12
    // W1 staging: tid<128, 4 lanes cover 16 k of one h row
    const int w_h  = (tid >> 2) & 31;
    const int w_kq = (tid & 3) * 4;
    const bool w_act = tid < 128;
    const bool h_ok  = w_act && (h0 + w_h) < HH;

    float4 a_r, h_r;

    a_r = *reinterpret_cast<const float4*>(&A[(m0 + a_m) * DD + a_kq]);
    h_r = make_float4(0.f, 0.f, 0.f, 0.f);
    if (h_ok)
        h_r = *reinterpret_cast<const float4*>(&W1[(h0 + w_h) * (2 * DD) + woff + w_kq]);

    // store tile 0 into buf 0
    {
        As[0][a_kq + 0][a_m] = a_r.x; As[0][a_kq + 1][a_m] = a_r.y;
        As[0][a_kq + 2][a_m] = a_r.z; As[0][a_kq + 3][a_m] = a_r.w;
        if (w_act) {
            u64 d0, d1, d2, d3;
            PACK2(d0, h_r.x, h_r.x); PACK2(d1, h_r.y, h_r.y);
            PACK2(d2, h_r.z, h_r.z); PACK2(d3, h_r.w, h_r.w);
            Hd[0][w_kq + 0][w_h] = d0; Hd[0][w_kq + 1][w_h] = d1;
            Hd[0][w_kq + 2][w_h] = d2; Hd[0][w_kq + 3][w_h] = d3;
        }
    }
    __syncthreads();

    u64 acc[2][2] = {};   // [ih][m-pair]

    const int NT = DD / 16;   // 25
    for (int t = 0; t < NT; t++) {
        const int p = t & 1;

        // prefetch tile t+1 from GMEM
        if (t + 1 < NT) {
            int k0 = (t + 1) * 16;
            a_r = *reinterpret_cast<const float4*>(&A[(m0 + a_m) * DD + k0 + a_kq]);
            if (h_ok)
                h_r = *reinterpret_cast<const float4*>(&W1[(h0 + w_h) * (2 * DD) + woff + k0 + w_kq]);
        }

        // compute buf p — software-pipelined LDS
        {
            ulonglong2 ma = *reinterpret_cast<const ulonglong2*>(&As[p][0][tx * 4]);
            ulonglong2 hp = *reinterpret_cast<const ulonglong2*>(&Hd[p][0][ty * 2]);
            #pragma unroll
            for (int kk = 0; kk < 16; kk++) {
                ulonglong2 nma, nhp;
                if (kk + 1 < 16) {
                    nma = *reinterpret_cast<const ulonglong2*>(&As[p][kk + 1][tx * 4]);
                    nhp = *reinterpret_cast<const ulonglong2*>(&Hd[p][kk + 1][ty * 2]);
                }
                FMA2(acc[0][0], hp.x, ma.x); FMA2(acc[0][1], hp.x, ma.y);
                FMA2(acc[1][0], hp.y, ma.x); FMA2(acc[1][1], hp.y, ma.y);
                ma = nma; hp = nhp;
            }
        }

        // stage tile t+1 into other buffer
        if (t + 1 < NT) {
            const int q = 1 - p;
            As[q][a_kq + 0][a_m] = a_r.x; As[q][a_kq + 1][a_m] = a_r.y;
            As[q][a_kq + 2][a_m] = a_r.z; As[q][a_kq + 3][a_m] = a_r.w;
            if (w_act) {
                u64 d0, d1, d2, d3;
                PACK2(d0, h_r.x, h_r.x); PACK2(d1, h_r.y, h_r.y);
                PACK2(d2, h_r.z, h_r.z); PACK2(d3, h_r.w, h_r.w);
                Hd[q][w_kq + 0][w_h] = d0; Hd[q][w_kq + 1][w_h] = d1;
                Hd[q][w_kq + 2][w_h] = d2; Hd[q][w_kq + 3][w_h] = d3;
            }
        }
        __syncthreads();
    }

    // epilogue: h >= 400 lanes have acc == 0 (weights staged as 0) -> writes zeros
    #pragma unroll
    for (int ih = 0; ih < 2; ih++) {
        int h = h0 + ty * 2 + ih;
        float2 p0 = *reinterpret_cast<float2*>(&acc[ih][0]);
        float2 p1 = *reinterpret_cast<float2*>(&acc[ih][1]);
        if (z && h < HH) {
            float b = b1[h];
            p0.x += b; p0.y += b; p1.x += b; p1.y += b;
        }
        *reinterpret_cast<float4*>(&outT[h * NS + m0 + tx * 4]) =
            make_float4(p0.x, p0.y, p1.x, p1.y);
    }
}

// ======================================================================
// Kernel 2: pair relu-dot + fused epilogue + last-block finalize.
//   v[i,j] = sum_h relu(g_hyT[h][i] + g_hxT[h][j]) * W2[h] + b2
// Tile 32i x 32j, 256 threads, thread tile 2i x 2j. BK=32, 13 tiles.
// k-pair interleaved, double-buffered, 1 sync/tile, pipelined LDS.
// Grid (16, 16) = 256 blocks.
// ======================================================================
__global__ void __launch_bounds__(256)
pair_kernel(const float* __restrict__ W2,
            const float* __restrict__ b2p,
            float* __restrict__ out) {
    const int j0  = blockIdx.x * 32;
    const int i0  = blockIdx.y * 32;
    const int tid = threadIdx.x;    // 256
    const int tx  = tid & 15;       // j pair: 2 j each
    const int ty  = tid >> 4;       // i pair: 2 i each (0..15)

    __shared__ __align__(16) u64 Yd[2][16][32][2];  // [buf][kp][i][k&1] dup'd (y,y)
    __shared__ __align__(16) u64 Xs[2][16][16][2];  // [buf][kp][j-pair][k&1] (xj0,xj1)
    __shared__ __align__(16) u64 Wp[2][16][2];      // [buf][kp][k&1] dup'd (w,w)

    // staging: BK=32 rows, 8 lanes cover 32 floats (128B) of one k row
    const int s_k = tid >> 3;       // 0..31
    const int s_q = tid & 7;        // quad index (i or j)
    const int s_kp  = s_k >> 1;
    const int s_par = s_k & 1;

    float4 y_r, x_r;
    float  w_r = 0.f;

    y_r = *reinterpret_cast<const float4*>(&g_hyT[s_k * NS + i0 + s_q * 4]);
    x_r = *reinterpret_cast<const float4*>(&g_hxT[s_k * NS + j0 + s_q * 4]);
    if (tid < 32) w_r = (tid < HH) ? W2[tid] : 0.f;

    // store tile 0 into buf 0
    {
        u64 d0, d1, d2, d3, xa, xb;
        PACK2(d0, y_r.x, y_r.x); PACK2(d1, y_r.y, y_r.y);
        PACK2(d2, y_r.z, y_r.z); PACK2(d3, y_r.w, y_r.w);
        Yd[0][s_kp][s_q * 4 + 0][s_par] = d0;
        Yd[0][s_kp][s_q * 4 + 1][s_par] = d1;
        Yd[0][s_kp][s_q * 4 + 2][s_par] = d2;
        Yd[0][s_kp][s_q * 4 + 3][s_par] = d3;
        PACK2(xa, x_r.x, x_r.y); PACK2(xb, x_r.z, x_r.w);
        Xs[0][s_kp][s_q * 2 + 0][s_par] = xa;
        Xs[0][s_kp][s_q * 2 + 1][s_par] = xb;
        if (tid < 32) {
            u64 wd; PACK2(wd, w_r, w_r);
            Wp[0][tid >> 1][tid & 1] = wd;
        }
    }
    __syncthreads();

    u64 acc[2] = {};   // [ii], each packs 2 j

    const int NT = HP / 32;   // 13
    for (int t = 0; t < NT; t++) {
        const int p = t & 1;

        // prefetch tile t+1 from GMEM (rows < HP are valid; pad rows are zero)
        if (t + 1 < NT) {
            int k0 = (t + 1) * 32;
            y_r = *reinterpret_cast<const float4*>(&g_hyT[(k0 + s_k) * NS + i0 + s_q * 4]);
            x_r = *reinterpret_cast<const float4*>(&g_hxT[(k0 + s_k) * NS + j0 + s_q * 4]);
            if (tid < 32) w_r = (k0 + tid < HH) ? W2[k0 + tid] : 0.f;
        }

        // compute buf p — software-pipelined LDS, 16 kp steps (32 k)
        {
            ulonglong2 xk  = *reinterpret_cast<const ulonglong2*>(&Xs[p][0][tx][0]);
            ulonglong2 yi0 = *reinterpret_cast<const ulonglong2*>(&Yd[p][0][ty * 2 + 0][0]);
            ulonglong2 yi1 = *reinterpret_cast<const ulonglong2*>(&Yd[p][0][ty * 2 + 1][0]);
            ulonglong2 wv  = *reinterpret_cast<const ulonglong2*>(&Wp[p][0][0]);
            #pragma unroll
            for (int kp = 0; kp < 16; kp++) {
                ulonglong2 nxk, nyi0, nyi1, nwv;
                if (kp + 1 < 16) {
                    nxk  = *reinterpret_cast<const ulonglong2*>(&Xs[p][kp + 1][tx][0]);
                    nyi0 = *reinterpret_cast<const ulonglong2*>(&Yd[p][kp + 1][ty * 2 + 0][0]);
                    nyi1 = *reinterpret_cast<const ulonglong2*>(&Yd[p][kp + 1][ty * 2 + 1][0]);
                    nwv  = *reinterpret_cast<const ulonglong2*>(&Wp[p][kp + 1][0]);
                }
                RELU_FMA2(acc[0], yi0.x, xk.x, wv.x);   // k even
                RELU_FMA2(acc[0], yi0.y, xk.y, wv.y);   // k odd
                RELU_FMA2(acc[1], yi1.x, xk.x, wv.x);
                RELU_FMA2(acc[1], yi1.y, xk.y, wv.y);
                xk = nxk; yi0 = nyi0; yi1 = nyi1; wv = nwv;
            }
        }

        // stage tile t+1 into other buffer
        if (t + 1 < NT) {
            const int q = 1 - p;
            u64 d0, d1, d2, d3, xa, xb;
            PACK2(d0, y_r.x, y_r.x); PACK2(d1, y_r.y, y_r.y);
            PACK2(d2, y_r.z, y_r.z); PACK2(d3, y_r.w, y_r.w);
            Yd[q][s_kp][s_q * 4 + 0][s_par] = d0;
            Yd[q][s_kp][s_q * 4 + 1][s_par] = d1;
            Yd[q][s_kp][s_q * 4 + 2][s_par] = d2;
            Yd[q][s_kp][s_q * 4 + 3][s_par] = d3;
            PACK2(xa, x_r.x, x_r.y); PACK2(xb, x_r.z, x_r.w);
            Xs[q][s_kp][s_q * 2 + 0][s_par] = xa;
            Xs[q][s_kp][s_q * 2 + 1][s_par] = xb;
            if (tid < 32) {
                u64 wd; PACK2(wd, w_r, w_r);
                Wp[q][tid >> 1][tid & 1] = wd;
            }
        }
        __syncthreads();
    }

    // ---- fused epilogue (accurate math) ----
    const float b2 = b2p[0];
    float tSum = 0.f, dSum = 0.f;

    #pragma unroll
    for (int ii = 0; ii < 2; ii++) {
        const int i = i0 + ty * 2 + ii;
        float2 pv = *reinterpret_cast<float2*>(&acc[ii]);
        float vq[2] = {pv.x, pv.y};
        float eRow = 0.f;
        #pragma unroll
        for (int q = 0; q < 2; q++) {
            float v = vq[q] + b2;
            float tt = fmaxf(v, 0.f) + log1pf(expf(-fabsf(v)));
            eRow += 1.f + expf(v);            // exp(softplus(v)) == 1 + e^v
            tSum += tt;
            if (j0 + tx * 2 + q == i) dSum += tt;
        }
        #pragma unroll
        for (int o = 8; o; o >>= 1)
            eRow += __shfl_down_sync(0xffffffffu, eRow, o, 16);
        if (tx == 0) atomicAdd(&g_expsum[i], eRow);
    }

    // block totals
    const int wid = tid >> 5, lane = tid & 31;
    #pragma unroll
    for (int o = 16; o; o >>= 1) {
        tSum += __shfl_down_sync(0xffffffffu, tSum, o);
        dSum += __shfl_down_sync(0xffffffffu, dSum, o);
    }
    __shared__ float wsum[8], wdia[8];
    if (lane == 0) { wsum[wid] = tSum; wdia[wid] = dSum; }
    __syncthreads();
    if (tid == 0) {
        float ts = 0.f, ds = 0.f;
        #pragma unroll
        for (int w = 0; w < 8; w++) { ts += wsum[w]; ds += wdia[w]; }
        atomicAdd(&g_tsum, (double)ts);
        atomicAdd(&g_dsum, (double)ds);
    }

    // ---- last block finalizes (double precision combine) ----
    __threadfence();
    __shared__ int ticket;
    if (tid == 0) ticket = atomicAdd(&g_cnt, 1);
    __syncthreads();
    if (ticket == 16 * 16 - 1) {
        double ls = log((double)g_expsum[tid]) + log((double)g_expsum[tid + 256]);
        #pragma unroll
        for (int o = 16; o; o >>= 1)
            ls += __shfl_down_sync(0xffffffffu, ls, o);
        __shared__ double lw[8];
        if (lane == 0) lw[wid] = ls;
        __syncthreads();
        if (tid == 0) {
            double lsum = 0.0;
            #pragma unroll
            for (int w = 0; w < 8; w++) lsum += lw[w];
            const double n = (double)NS;
            double t0_mean = g_dsum / n;
            out[0] = (float)(t0_mean - (lsum / n - log(n)));   // lower bound
            out[1] = (float)(t0_mean - g_tsum / (n * n));      // upper bound
            g_cnt = 0;
        }
    }
}

// ======================================================================
extern "C" void kernel_launch(void* const* d_in, const int* in_sizes, int n_in,
                              void* d_out, int out_size) {
    const float* x  = (const float*)d_in[0];
    const float* y  = (const float*)d_in[1];
    const float* W1 = (const float*)d_in[2];
    const float* b1 = (const float*)d_in[3];
    const float* W2 = (const float*)d_in[4];
    const float* b2 = (const float*)d_in[5];
    float* out = (float*)d_out;

    dim3 ggrid(NS / 64, HP / 32, 2);          // (8, 13, 2) = 208 blocks
    gemm_h_kernel<<<ggrid, 256>>>(x, y, W1, b1);

    dim3 pgrid(NS / 32, NS / 32);             // (16, 16) = 256 blocks
    pair_kernel<<<pgrid, 256>>>(W2, b2, out);
}

// round 8
// speedup vs baseline: 1.2228x; 1.2228x over previous
#include <cuda_runtime.h>
#include <math.h>

#define NS 512
#define DD 400
#define HH 400
#define HP 416   // padded hidden dim (13 * 32); pad rows stay statically zero

typedef unsigned long long u64;

// ---- scratch (no allocations; __device__ globals are zero-initialized) ----
__device__ float  g_hxT[HP * NS];   // [h][sample]; rows 400..415 never written (zero)
__device__ float  g_hyT[HP * NS];   // b1 folded in; rows 400..415 zero
__device__ float  g_rx[NS];         // sum_h hx[j,h]*W2[h]      (re-zeroed by finalize)
__device__ float  g_ry[NS];         // sum_h (hy[i,h]+b1)*W2[h] (re-zeroed by finalize)
__device__ float  g_expsum[NS];     // per-row sum of exp(T1) = 1 + e^v
__device__ double g_tsum;           // sum of all T1
__device__ double g_dsum;           // sum of diag T1 (== T0 sum)
__device__ int    g_cnt = 0;

// ---- packed f32x2 helpers (sm_10x) ----
#define PACK2(d, lo, hi) \
    asm("mov.b64 %0, {%1,%2};" : "=l"(d) : "f"(lo), "f"(hi))
#define FMA2(acc, a, b) \
    asm("fma.rn.f32x2 %0, %1, %2, %0;" : "+l"(acc) : "l"(a), "l"(b))
// acc2 += |y2 + x2| * w2   (componentwise; abs via sign-mask AND, no unpacking)
#define ABS_FMA2(acc, y2, x2, w2)                       \
    asm("{\n\t"                                         \
        ".reg .b64 t;\n\t"                              \
        "add.rn.f32x2 t, %1, %2;\n\t"                   \
        "and.b64 t, t, 0x7FFFFFFF7FFFFFFF;\n\t"         \
        "fma.rn.f32x2 %0, t, %3, %0;\n\t"               \
        "}" : "+l"(acc) : "l"(y2), "l"(x2), "l"(w2))

// ======================================================================
// Kernel 1: dual GEMM, transposed output + W2 row-dot epilogue.
//   z=0: g_hxT[h][m] = sum_k x[m,k] W1[h,k];          g_rx[m] += dot w/ W2
//   z=1: g_hyT[h][m] = sum_k y[m,k] W1[h,400+k] + b1; g_ry[m] += dot w/ W2
// Tile 64m x 32h, BK=16, 128 threads, thread tile 2h x 8m.
// Coalesced global loads (4 lanes cover 16 contiguous k of one row).
// Grid (8 m, 13 h, 2 z) = 208 blocks.
// ======================================================================
__global__ void __launch_bounds__(128)
gemm_h_kernel(const float* __restrict__ x,
              const float* __restrict__ y,
              const float* __restrict__ W1,
              const float* __restrict__ b1,
              const float* __restrict__ W2) {
    const int z = blockIdx.z;

    if (z == 0 && blockIdx.x == 0 && blockIdx.y == 0) {
        #pragma unroll
        for (int r = 0; r < 4; r++) g_expsum[threadIdx.x + r * 128] = 0.f;
        if (threadIdx.x == 0) { g_tsum = 0.0; g_dsum = 0.0; g_cnt = 0; }
    }

    const float* A   = z ? y : x;
    const int   woff = z ? DD : 0;
    float*      outT = z ? g_hyT : g_hxT;
    float*      rdot = z ? g_ry  : g_rx;

    const int m0 = blockIdx.x * 64;
    const int h0 = blockIdx.y * 32;

    __shared__ __align__(16) float As[16][68];  // [k][m] (+pad vs bank conflicts)
    __shared__ __align__(16) u64   Hd[16][34];  // [k][h] dup'd (w,w) (+pad)

    const int tid = threadIdx.x;       // 128
    const int tx  = tid & 7;           // m octet: 8 m each
    const int ty  = tid >> 3;          // h pair: 2 h each (0..15)

    // coalesced staging: 4 lanes cover 16 contiguous k of one row
    const int a_row = tid >> 2;        // 0..31 (+32 for second)
    const int a_q   = (tid & 3) * 4;   // k quad
    const bool h_ok = (h0 + a_row) < HH;

    float4 a0, a1, hw;

    a0 = *reinterpret_cast<const float4*>(&A[(m0 + a_row) * DD + a_q]);
    a1 = *reinterpret_cast<const float4*>(&A[(m0 + a_row + 32) * DD + a_q]);
    hw = make_float4(0.f, 0.f, 0.f, 0.f);
    if (h_ok)
        hw = *reinterpret_cast<const float4*>(&W1[(h0 + a_row) * (2 * DD) + woff + a_q]);

    u64 acc[2][4] = {};   // [ih][m-pair]

    const int NT = DD / 16;   // 25
    for (int t = 0; t < NT; t++) {
        // store staged tile
        As[a_q + 0][a_row] = a0.x; As[a_q + 1][a_row] = a0.y;
        As[a_q + 2][a_row] = a0.z; As[a_q + 3][a_row] = a0.w;
        As[a_q + 0][a_row + 32] = a1.x; As[a_q + 1][a_row + 32] = a1.y;
        As[a_q + 2][a_row + 32] = a1.z; As[a_q + 3][a_row + 32] = a1.w;
        u64 d0, d1, d2, d3;
        PACK2(d0, hw.x, hw.x); PACK2(d1, hw.y, hw.y);
        PACK2(d2, hw.z, hw.z); PACK2(d3, hw.w, hw.w);
        Hd[a_q + 0][a_row] = d0; Hd[a_q + 1][a_row] = d1;
        Hd[a_q + 2][a_row] = d2; Hd[a_q + 3][a_row] = d3;
        __syncthreads();

        // prefetch next tile
        if (t + 1 < NT) {
            int k0 = (t + 1) * 16;
            a0 = *reinterpret_cast<const float4*>(&A[(m0 + a_row) * DD + k0 + a_q]);
            a1 = *reinterpret_cast<const float4*>(&A[(m0 + a_row + 32) * DD + k0 + a_q]);
            if (h_ok)
                hw = *reinterpret_cast<const float4*>(&W1[(h0 + a_row) * (2 * DD) + woff + k0 + a_q]);
        }

        #pragma unroll
        for (int kk = 0; kk < 16; kk++) {
            ulonglong2 hp = *reinterpret_cast<const ulonglong2*>(&Hd[kk][ty * 2]);
            ulonglong2 ma = *reinterpret_cast<const ulonglong2*>(&As[kk][tx * 8 + 0]);
            ulonglong2 mb = *reinterpret_cast<const ulonglong2*>(&As[kk][tx * 8 + 4]);
            FMA2(acc[0][0], hp.x, ma.x); FMA2(acc[0][1], hp.x, ma.y);
            FMA2(acc[0][2], hp.x, mb.x); FMA2(acc[0][3], hp.x, mb.y);
            FMA2(acc[1][0], hp.y, ma.x); FMA2(acc[1][1], hp.y, ma.y);
            FMA2(acc[1][2], hp.y, mb.x); FMA2(acc[1][3], hp.y, mb.y);
        }
        __syncthreads();
    }

    // ---- epilogue: b1 add, transposed store, W2 row-dot atomics ----
    float vals[2][8];
    float wv[2];
    #pragma unroll
    for (int ih = 0; ih < 2; ih++) {
        const int h = h0 + ty * 2 + ih;
        const bool valid = h < HH;
        const float b = (z && valid) ? b1[h] : 0.f;
        wv[ih] = valid ? W2[h] : 0.f;
        #pragma unroll
        for (int mp = 0; mp < 4; mp++) {
            float2 pv = *reinterpret_cast<float2*>(&acc[ih][mp]);
            vals[ih][mp * 2 + 0] = pv.x + b;
            vals[ih][mp * 2 + 1] = pv.y + b;
        }
        if (valid) {
            float* o = &outT[h * NS + m0 + tx * 8];
            *reinterpret_cast<float4*>(o + 0) =
                make_float4(vals[ih][0], vals[ih][1], vals[ih][2], vals[ih][3]);
            *reinterpret_cast<float4*>(o + 4) =
                make_float4(vals[ih][4], vals[ih][5], vals[ih][6], vals[ih][7]);
        }
    }
    #pragma unroll
    for (int mm = 0; mm < 8; mm++) {
        float p = vals[0][mm] * wv[0] + vals[1][mm] * wv[1];
        atomicAdd(&rdot[m0 + tx * 8 + mm], p);
    }
}

// ======================================================================
// Kernel 2: pair abs-dot + fused epilogue + last-block finalize.
//   A[i,j] = sum_h |g_hyT[h][i] + g_hxT[h][j]| * (W2[h]/2)
//   v[i,j] = 0.5*(g_ry[i] + g_rx[j]) + A[i,j] + b2      (== pre-softplus score)
// Tile 32i x 64j, 256 threads, thread tile 2i x 4j. BK=16, 26 tiles.
// Grid (8, 16) = 128 blocks.
// ======================================================================
__global__ void __launch_bounds__(256)
pair_kernel(const float* __restrict__ W2,
            const float* __restrict__ b2p,
            float* __restrict__ out) {
    const int j0  = blockIdx.x * 64;
    const int i0  = blockIdx.y * 32;
    const int tid = threadIdx.x;    // 256
    const int tx  = tid & 15;       // j group: 4 j each
    const int ty  = tid >> 4;       // i pair: 2 i each (0..15)

    // k-pair interleaved: [kp][row][k&1]
    __shared__ __align__(16) u64 Yd[8][32][2];  // dup'd (y,y) per i
    __shared__ __align__(16) u64 Xs[8][32][2];  // packed (xj0,xj1) per j-pair
    __shared__ __align__(16) u64 Wp[8][2];      // dup'd (w/2, w/2)

    const int s_p = tid & 15;       // i-pair / j-quad index
    const int s_k = tid >> 4;       // k within tile (0..15)

    float2 y_r;
    float4 x_r;
    float  w_r = 0.f;

    // load tile 0 (rows < HP valid; pad rows are zero)
    y_r = *reinterpret_cast<const float2*>(&g_hyT[s_k * NS + i0 + s_p * 2]);
    x_r = *reinterpret_cast<const float4*>(&g_hxT[s_k * NS + j0 + s_p * 4]);
    if (tid < 16) w_r = (tid < HH) ? W2[tid] * 0.5f : 0.f;

    u64 acc[2][2] = {};   // [ii][j-pair]

    const int NT = HP / 16;   // 26
    for (int t = 0; t < NT; t++) {
        // store staged tile
        {
            u64 yd0, yd1, xa, xb;
            PACK2(yd0, y_r.x, y_r.x);
            PACK2(yd1, y_r.y, y_r.y);
            Yd[s_k >> 1][s_p * 2 + 0][s_k & 1] = yd0;
            Yd[s_k >> 1][s_p * 2 + 1][s_k & 1] = yd1;
            PACK2(xa, x_r.x, x_r.y);
            PACK2(xb, x_r.z, x_r.w);
            Xs[s_k >> 1][s_p * 2 + 0][s_k & 1] = xa;
            Xs[s_k >> 1][s_p * 2 + 1][s_k & 1] = xb;
            if (tid < 16) {
                u64 wd; PACK2(wd, w_r, w_r);
                Wp[tid >> 1][tid & 1] = wd;
            }
        }
        __syncthreads();

        // prefetch next tile
        if (t + 1 < NT) {
            int k0 = (t + 1) * 16;
            y_r = *reinterpret_cast<const float2*>(&g_hyT[(k0 + s_k) * NS + i0 + s_p * 2]);
            x_r = *reinterpret_cast<const float4*>(&g_hxT[(k0 + s_k) * NS + j0 + s_p * 4]);
            if (tid < 16) w_r = (k0 + tid < HH) ? W2[k0 + tid] * 0.5f : 0.f;
        }

        // compute: 8 kp steps, each covering 2 k
        #pragma unroll
        for (int kp = 0; kp < 8; kp++) {
            ulonglong2 wv = *reinterpret_cast<const ulonglong2*>(&Wp[kp][0]);
            ulonglong2 ya = *reinterpret_cast<const ulonglong2*>(&Yd[kp][ty * 2 + 0][0]);
            ulonglong2 yb = *reinterpret_cast<const ulonglong2*>(&Yd[kp][ty * 2 + 1][0]);
            ulonglong2 xa = *reinterpret_cast<const ulonglong2*>(&Xs[kp][tx * 2 + 0][0]);
            ulonglong2 xb = *reinterpret_cast<const ulonglong2*>(&Xs[kp][tx * 2 + 1][0]);
            ABS_FMA2(acc[0][0], ya.x, xa.x, wv.x);   // k even
            ABS_FMA2(acc[0][0], ya.y, xa.y, wv.y);   // k odd
            ABS_FMA2(acc[0][1], ya.x, xb.x, wv.x);
            ABS_FMA2(acc[0][1], ya.y, xb.y, wv.y);
            ABS_FMA2(acc[1][0], yb.x, xa.x, wv.x);
            ABS_FMA2(acc[1][0], yb.y, xa.y, wv.y);
            ABS_FMA2(acc[1][1], yb.x, xb.x, wv.x);
            ABS_FMA2(acc[1][1], yb.y, xb.y, wv.y);
        }
        __syncthreads();
    }

    // ---- fused epilogue ----
    const float b2 = b2p[0];
    const float4 rx = *reinterpret_cast<const float4*>(&g_rx[j0 + tx * 4]);
    const float rxq[4] = {rx.x, rx.y, rx.z, rx.w};
    float tSum = 0.f, dSum = 0.f;

    #pragma unroll
    for (int ii = 0; ii < 2; ii++) {
        const int i = i0 + ty * 2 + ii;
        const float ry = g_ry[i];
        float2 p01 = *reinterpret_cast<float2*>(&acc[ii][0]);
        float2 p23 = *reinterpret_cast<float2*>(&acc[ii][1]);
        float aq[4] = {p01.x, p01.y, p23.x, p23.y};
        float eRow = 0.f;
        #pragma unroll
        for (int q = 0; q < 4; q++) {
            float v = 0.5f * (ry + rxq[q]) + aq[q] + b2;
            float tt = fmaxf(v, 0.f) + log1pf(expf(-fabsf(v)));
            eRow += 1.f + expf(v);            // exp(softplus(v)) == 1 + e^v
            tSum += tt;
            if (j0 + tx * 4 + q == i) dSum += tt;
        }
        #pragma unroll
        for (int o = 8; o; o >>= 1)
            eRow += __shfl_down_sync(0xffffffffu, eRow, o, 16);
        if (tx == 0) atomicAdd(&g_expsum[i], eRow);
    }

    // block totals
    const int wid = tid >> 5, lane = tid & 31;
    #pragma unroll
    for (int o = 16; o; o >>= 1) {
        tSum += __shfl_down_sync(0xffffffffu, tSum, o);
        dSum += __shfl_down_sync(0xffffffffu, dSum, o);
    }
    __shared__ float wsum[8], wdia[8];
    if (lane == 0) { wsum[wid] = tSum; wdia[wid] = dSum; }
    __syncthreads();
    if (tid == 0) {
        float ts = 0.f, ds = 0.f;
        #pragma unroll
        for (int w = 0; w < 8; w++) { ts += wsum[w]; ds += wdia[w]; }
        atomicAdd(&g_tsum, (double)ts);
        atomicAdd(&g_dsum, (double)ds);
    }

    // ---- last block finalizes (double precision combine) ----
    __threadfence();
    __shared__ int ticket;
    if (tid == 0) ticket = atomicAdd(&g_cnt, 1);
    __syncthreads();
    if (ticket == 8 * 16 - 1) {
        // re-zero rdot accumulators for the next replay (all readers are done)
        g_rx[tid] = 0.f; g_rx[tid + 256] = 0.f;
        g_ry[tid] = 0.f; g_ry[tid + 256] = 0.f;

        double ls = log((double)g_expsum[tid]) + log((double)g_expsum[tid + 256]);
        #pragma unroll
        for (int o = 16; o; o >>= 1)
            ls += __shfl_down_sync(0xffffffffu, ls, o);
        __shared__ double lw[8];
        if (lane == 0) lw[wid] = ls;
        __syncthreads();
        if (tid == 0) {
            double lsum = 0.0;
            #pragma unroll
            for (int w = 0; w < 8; w++) lsum += lw[w];
            const double n = (double)NS;
            double t0_mean = g_dsum / n;
            out[0] = (float)(t0_mean - (lsum / n - log(n)));   // lower bound
            out[1] = (float)(t0_mean - g_tsum / (n * n));      // upper bound
            g_cnt = 0;
        }
    }
}

// ======================================================================
extern "C" void kernel_launch(void* const* d_in, const int* in_sizes, int n_in,
                              void* d_out, int out_size) {
    const float* x  = (const float*)d_in[0];
    const float* y  = (const float*)d_in[1];
    const float* W1 = (const float*)d_in[2];
    const float* b1 = (const float*)d_in[3];
    const float* W2 = (const float*)d_in[4];
    const float* b2 = (const float*)d_in[5];
    float* out = (float*)d_out;

    dim3 ggrid(NS / 64, HP / 32, 2);          // (8, 13, 2) = 208 blocks
    gemm_h_kernel<<<ggrid, 128>>>(x, y, W1, b1, W2);

    dim3 pgrid(NS / 64, NS / 32);             // (8, 16) = 128 blocks
    pair_kernel<<<pgrid, 256>>>(W2, b2, out);
}

// round 10
// speedup vs baseline: 1.7564x; 1.4364x over previous
#include <cuda_runtime.h>
#include <math.h>

#define NS 512
#define DD 400
#define HH 400
#define HP 416   // padded hidden dim (13 * 32); pad rows stay statically zero

typedef unsigned long long u64;

// ---- scratch (no allocations; __device__ globals are zero-initialized) ----
__device__ float  g_hxT[HP * NS];   // [h][sample]; rows 400..415 never written (zero)
__device__ float  g_hyT[HP * NS];   // b1 folded in; rows 400..415 zero
__device__ float  g_rx[NS];         // sum_h hx[j,h]*W2[h]      (re-zeroed by finalize)
__device__ float  g_ry[NS];         // sum_h (hy[i,h]+b1)*W2[h] (re-zeroed by finalize)
__device__ float  g_expsum[NS];     // per-row sum of exp(T1) = 1 + e^v
__device__ double g_tsum;           // sum of all T1
__device__ double g_dsum;           // sum of diag T1 (== T0 sum)
__device__ int    g_cnt = 0;

// ---- packed f32x2 helpers (sm_10x) ----
#define PACK2(d, lo, hi) \
    asm("mov.b64 %0, {%1,%2};" : "=l"(d) : "f"(lo), "f"(hi))
#define FMA2(acc, a, b) \
    asm("fma.rn.f32x2 %0, %1, %2, %0;" : "+l"(acc) : "l"(a), "l"(b))
// acc2 += |y2 + x2| * w2   (componentwise; abs via sign-mask AND, no unpacking)
#define ABS_FMA2(acc, y2, x2, w2)                       \
    asm("{\n\t"                                         \
        ".reg .b64 t;\n\t"                              \
        "add.rn.f32x2 t, %1, %2;\n\t"                   \
        "and.b64 t, t, 0x7FFFFFFF7FFFFFFF;\n\t"         \
        "fma.rn.f32x2 %0, t, %3, %0;\n\t"               \
        "}" : "+l"(acc) : "l"(y2), "l"(x2), "l"(w2))

// ======================================================================
// Kernel 1: dual GEMM, transposed output + W2 row-dot epilogue.
//   z=0: g_hxT[h][m] = sum_k x[m,k] W1[h,k];          g_rx[m] += dot w/ W2
//   z=1: g_hyT[h][m] = sum_k y[m,k] W1[h,400+k] + b1; g_ry[m] += dot w/ W2
// Tile 64m x 32h, BK=16, 128 threads, thread tile 4h x 4m.
// All compute LDS are broadcast or 128B-per-8-lane (conflict-free).
// Row-dots: smem ATOMS pre-reduction, then 64 global atomics/block.
// Grid (8 m, 13 h, 2 z) = 208 blocks.
// ======================================================================
__global__ void __launch_bounds__(128)
gemm_h_kernel(const float* __restrict__ x,
              const float* __restrict__ y,
              const float* __restrict__ W1,
              const float* __restrict__ b1,
              const float* __restrict__ W2) {
    const int z = blockIdx.z;

    if (z == 0 && blockIdx.x == 0 && blockIdx.y == 0) {
        #pragma unroll
        for (int r = 0; r < 4; r++) g_expsum[threadIdx.x + r * 128] = 0.f;
        if (threadIdx.x == 0) { g_tsum = 0.0; g_dsum = 0.0; g_cnt = 0; }
    }

    const float* A   = z ? y : x;
    const int   woff = z ? DD : 0;
    float*      outT = z ? g_hyT : g_hxT;
    float*      rdot = z ? g_ry  : g_rx;

    const int m0 = blockIdx.x * 64;
    const int h0 = blockIdx.y * 32;

    __shared__ __align__(16) float As[16][64];  // [k][m]
    __shared__ __align__(16) u64   Hd[16][32];  // [k][h] dup'd (w,w)
    __shared__ float rsum[64];

    const int tid = threadIdx.x;       // 128
    const int tx  = tid & 15;          // m quad: 4 m each
    const int ty  = tid >> 4;          // h quad: 4 h each (0..7)

    // coalesced staging: 4 lanes cover 16 contiguous k of one row
    const int s_row = tid >> 2;        // 0..31
    const int s_q   = (tid & 3) * 4;   // k quad 0,4,8,12
    const bool h_ok = (h0 + s_row) < HH;

    float4 a0, a1, hw;

    a0 = *reinterpret_cast<const float4*>(&A[(m0 + s_row) * DD + s_q]);
    a1 = *reinterpret_cast<const float4*>(&A[(m0 + s_row + 32) * DD + s_q]);
    hw = make_float4(0.f, 0.f, 0.f, 0.f);
    if (h_ok)
        hw = *reinterpret_cast<const float4*>(&W1[(h0 + s_row) * (2 * DD) + woff + s_q]);

    u64 acc[4][2] = {};   // [ih][m-pair]

    const int NT = DD / 16;   // 25
    for (int t = 0; t < NT; t++) {
        // store staged tile
        As[s_q + 0][s_row] = a0.x; As[s_q + 1][s_row] = a0.y;
        As[s_q + 2][s_row] = a0.z; As[s_q + 3][s_row] = a0.w;
        As[s_q + 0][s_row + 32] = a1.x; As[s_q + 1][s_row + 32] = a1.y;
        As[s_q + 2][s_row + 32] = a1.z; As[s_q + 3][s_row + 32] = a1.w;
        u64 d0, d1, d2, d3;
        PACK2(d0, hw.x, hw.x); PACK2(d1, hw.y, hw.y);
        PACK2(d2, hw.z, hw.z); PACK2(d3, hw.w, hw.w);
        Hd[s_q + 0][s_row] = d0; Hd[s_q + 1][s_row] = d1;
        Hd[s_q + 2][s_row] = d2; Hd[s_q + 3][s_row] = d3;
        __syncthreads();

        // prefetch next tile
        if (t + 1 < NT) {
            int k0 = (t + 1) * 16;
            a0 = *reinterpret_cast<const float4*>(&A[(m0 + s_row) * DD + k0 + s_q]);
            a1 = *reinterpret_cast<const float4*>(&A[(m0 + s_row + 32) * DD + k0 + s_q]);
            if (h_ok)
                hw = *reinterpret_cast<const float4*>(&W1[(h0 + s_row) * (2 * DD) + woff + k0 + s_q]);
        }

        #pragma unroll
        for (int kk = 0; kk < 16; kk++) {
            // Hd: lanes 0-15 share ty -> broadcast.  As: 8 lanes span 128B.
            ulonglong2 h01 = *reinterpret_cast<const ulonglong2*>(&Hd[kk][ty * 4 + 0]);
            ulonglong2 h23 = *reinterpret_cast<const ulonglong2*>(&Hd[kk][ty * 4 + 2]);
            ulonglong2 mm  = *reinterpret_cast<const ulonglong2*>(&As[kk][tx * 4]);
            FMA2(acc[0][0], h01.x, mm.x); FMA2(acc[0][1], h01.x, mm.y);
            FMA2(acc[1][0], h01.y, mm.x); FMA2(acc[1][1], h01.y, mm.y);
            FMA2(acc[2][0], h23.x, mm.x); FMA2(acc[2][1], h23.x, mm.y);
            FMA2(acc[3][0], h23.y, mm.x); FMA2(acc[3][1], h23.y, mm.y);
        }
        __syncthreads();
    }

    // ---- epilogue: b1 add, transposed store, row-dot via smem reduction ----
    if (tid < 64) rsum[tid] = 0.f;
    __syncthreads();

    float part[4] = {0.f, 0.f, 0.f, 0.f};
    #pragma unroll
    for (int ih = 0; ih < 4; ih++) {
        const int h = h0 + ty * 4 + ih;
        const bool valid = h < HH;
        const float b  = (z && valid) ? b1[h] : 0.f;
        const float wv = valid ? W2[h] : 0.f;
        float2 p0 = *reinterpret_cast<float2*>(&acc[ih][0]);
        float2 p1 = *reinterpret_cast<float2*>(&acc[ih][1]);
        float v0 = p0.x + b, v1 = p0.y + b, v2 = p1.x + b, v3 = p1.y + b;
        if (valid)
            *reinterpret_cast<float4*>(&outT[h * NS + m0 + tx * 4]) =
                make_float4(v0, v1, v2, v3);
        part[0] += v0 * wv; part[1] += v1 * wv;
        part[2] += v2 * wv; part[3] += v3 * wv;
    }
    #pragma unroll
    for (int mm = 0; mm < 4; mm++)
        atomicAdd(&rsum[tx * 4 + mm], part[mm]);
    __syncthreads();
    if (tid < 64) atomicAdd(&rdot[m0 + tid], rsum[tid]);
}

// ======================================================================
// Kernel 2: pair abs-dot + fused epilogue + last-block finalize.
//   A[i,j] = sum_h |g_hyT[h][i] + g_hxT[h][j]| * (W2[h]/2)
//   v[i,j] = 0.5*(g_ry[i] + g_rx[j]) + A[i,j] + b2
// Tile 32i x 32j, 128 threads, thread tile 2i x 4j. BK=16, 26 tiles.
// Xs plain floats (128B per 8 lanes), Yd/Wd dup'd (broadcast) -> no conflicts.
// Grid (16, 16) = 256 blocks.
// ======================================================================
__global__ void __launch_bounds__(128)
pair_kernel(const float* __restrict__ W2,
            const float* __restrict__ b2p,
            float* __restrict__ out) {
    const int j0  = blockIdx.x * 32;
    const int i0  = blockIdx.y * 32;
    const int tid = threadIdx.x;    // 128
    const int tx  = tid & 7;        // j quad: 4 j each
    const int ty  = tid >> 3;       // i pair: 2 i each (0..15)

    __shared__ __align__(16) float Xs[16][32];   // [k][j]
    __shared__ __align__(16) u64   Yd[16][32];   // [k][i] dup'd (y,y)
    __shared__ __align__(16) u64   Wd[16];       // dup'd (w/2, w/2)

    // staging: 8 lanes cover one 32-float k-row (128B), 16 k rows
    const int s_k = tid >> 3;       // 0..15
    const int s_q = tid & 7;        // float4 index

    float4 y_r, x_r;
    float  w_r = 0.f;

    y_r = *reinterpret_cast<const float4*>(&g_hyT[s_k * NS + i0 + s_q * 4]);
    x_r = *reinterpret_cast<const float4*>(&g_hxT[s_k * NS + j0 + s_q * 4]);
    if (tid < 16) w_r = (tid < HH) ? W2[tid] * 0.5f : 0.f;

    u64 acc[2][2] = {};   // [ii][j-pair]

    const int NT = HP / 16;   // 26
    for (int t = 0; t < NT; t++) {
        // store staged tile
        *reinterpret_cast<float4*>(&Xs[s_k][s_q * 4]) = x_r;
        u64 d0, d1, d2, d3;
        PACK2(d0, y_r.x, y_r.x); PACK2(d1, y_r.y, y_r.y);
        PACK2(d2, y_r.z, y_r.z); PACK2(d3, y_r.w, y_r.w);
        Yd[s_k][s_q * 4 + 0] = d0; Yd[s_k][s_q * 4 + 1] = d1;
        Yd[s_k][s_q * 4 + 2] = d2; Yd[s_k][s_q * 4 + 3] = d3;
        if (tid < 16) {
            u64 wd; PACK2(wd, w_r, w_r);
            Wd[tid] = wd;
        }
        __syncthreads();

        // prefetch next tile
        if (t + 1 < NT) {
            int k0 = (t + 1) * 16;
            y_r = *reinterpret_cast<const float4*>(&g_hyT[(k0 + s_k) * NS + i0 + s_q * 4]);
            x_r = *reinterpret_cast<const float4*>(&g_hxT[(k0 + s_k) * NS + j0 + s_q * 4]);
            if (tid < 16) w_r = (k0 + tid < HH) ? W2[k0 + tid] * 0.5f : 0.f;
        }

        #pragma unroll
        for (int kk = 0; kk < 16; kk++) {
            // Xs: lanes 0-7 cover 128B.  Yd: lanes 0-7 share ty -> broadcast.
            ulonglong2 xa = *reinterpret_cast<const ulonglong2*>(&Xs[kk][tx * 4]);
            ulonglong2 yp = *reinterpret_cast<const ulonglong2*>(&Yd[kk][ty * 2]);
            u64 w2 = Wd[kk];
            ABS_FMA2(acc[0][0], yp.x, xa.x, w2);
            ABS_FMA2(acc[0][1], yp.x, xa.y, w2);
            ABS_FMA2(acc[1][0], yp.y, xa.x, w2);
            ABS_FMA2(acc[1][1], yp.y, xa.y, w2);
        }
        __syncthreads();
    }

    // ---- fused epilogue ----
    const float b2 = b2p[0];
    const float4 rx = *reinterpret_cast<const float4*>(&g_rx[j0 + tx * 4]);
    const float rxq[4] = {rx.x, rx.y, rx.z, rx.w};
    float tSum = 0.f, dSum = 0.f;

    #pragma unroll
    for (int ii = 0; ii < 2; ii++) {
        const int i = i0 + ty * 2 + ii;
        const float ry = g_ry[i];
        float2 p01 = *reinterpret_cast<float2*>(&acc[ii][0]);
        float2 p23 = *reinterpret_cast<float2*>(&acc[ii][1]);
        float aq[4] = {p01.x, p01.y, p23.x, p23.y};
        float eRow = 0.f;
        #pragma unroll
        for (int q = 0; q < 4; q++) {
            float v = 0.5f * (ry + rxq[q]) + aq[q] + b2;
            float tt = fmaxf(v, 0.f) + log1pf(expf(-fabsf(v)));
            eRow += 1.f + expf(v);            // exp(softplus(v)) == 1 + e^v
            tSum += tt;
            if (j0 + tx * 4 + q == i) dSum += tt;
        }
        // row partial over 8 j-lanes (consecutive: tid = ty*8 + tx)
        #pragma unroll
        for (int o = 4; o; o >>= 1)
            eRow += __shfl_down_sync(0xffffffffu, eRow, o, 8);
        if (tx == 0) atomicAdd(&g_expsum[i], eRow);
    }

    // block totals
    const int wid = tid >> 5, lane = tid & 31;
    #pragma unroll
    for (int o = 16; o; o >>= 1) {
        tSum += __shfl_down_sync(0xffffffffu, tSum, o);
        dSum += __shfl_down_sync(0xffffffffu, dSum, o);
    }
    __shared__ float wsum[4], wdia[4];
    if (lane == 0) { wsum[wid] = tSum; wdia[wid] = dSum; }
    __syncthreads();
    if (tid == 0) {
        float ts = wsum[0] + wsum[1] + wsum[2] + wsum[3];
        float ds = wdia[0] + wdia[1] + wdia[2] + wdia[3];
        atomicAdd(&g_tsum, (double)ts);
        atomicAdd(&g_dsum, (double)ds);
    }

    // ---- last block finalizes (double precision combine) ----
    __threadfence();
    __shared__ int ticket;
    if (tid == 0) ticket = atomicAdd(&g_cnt, 1);
    __syncthreads();
    if (ticket == 16 * 16 - 1) {
        // re-zero rdot accumulators for the next graph replay
        #pragma unroll
        for (int r = 0; r < 4; r++) {
            g_rx[tid + r * 128] = 0.f;
            g_ry[tid + r * 128] = 0.f;
        }
        double ls = 0.0;
        #pragma unroll
        for (int r = 0; r < 4; r++)
            ls += log((double)g_expsum[tid + r * 128]);
        #pragma unroll
        for (int o = 16; o; o >>= 1)
            ls += __shfl_down_sync(0xffffffffu, ls, o);
        __shared__ double lw[4];
        if (lane == 0) lw[wid] = ls;
        __syncthreads();
        if (tid == 0) {
            double lsum = lw[0] + lw[1] + lw[2] + lw[3];
            const double n = (double)NS;
            double t0_mean = g_dsum / n;
            out[0] = (float)(t0_mean - (lsum / n - log(n)));   // lower bound
            out[1] = (float)(t0_mean - g_tsum / (n * n));      // upper bound
            g_cnt = 0;
        }
    }
}

// ======================================================================
extern "C" void kernel_launch(void* const* d_in, const int* in_sizes, int n_in,
                              void* d_out, int out_size) {
    const float* x  = (const float*)d_in[0];
    const float* y  = (const float*)d_in[1];
    const float* W1 = (const float*)d_in[2];
    const float* b1 = (const float*)d_in[3];
    const float* W2 = (const float*)d_in[4];
    const float* b2 = (const float*)d_in[5];
    float* out = (float*)d_out;

    dim3 ggrid(NS / 64, HP / 32, 2);          // (8, 13, 2) = 208 blocks
    gemm_h_kernel<<<ggrid, 128>>>(x, y, W1, b1, W2);

    dim3 pgrid(NS / 32, NS / 32);             // (16, 16) = 256 blocks
    pair_kernel<<<pgrid, 128>>>(W2, b2, out);
}